// round 13
// baseline (speedup 1.0000x reference)
#include <cuda_runtime.h>
#include <cuda_bf16.h>
#include <stdint.h>
#include <math.h>

#define NN    256
#define BATCH 16
#define WID   64
#define MD    16
#define HSZ   (BATCH*WID*NN*NN)

typedef unsigned long long u64;
typedef unsigned int u32;

// ---------------- tensor-core helpers ----------------
__device__ __forceinline__ u32 sptr(const void* p) {
    return (u32)__cvta_generic_to_shared(p);
}
__device__ __forceinline__ void ldsm_x4(u32* r, u32 a) {
    asm volatile("ldmatrix.sync.aligned.m8n8.x4.shared.b16 {%0,%1,%2,%3},[%4];"
                 : "=r"(r[0]), "=r"(r[1]), "=r"(r[2]), "=r"(r[3]) : "r"(a));
}
__device__ __forceinline__ void ldsm_x2(u32 &r0, u32 &r1, u32 a) {
    asm volatile("ldmatrix.sync.aligned.m8n8.x2.shared.b16 {%0,%1},[%2];"
                 : "=r"(r0), "=r"(r1) : "r"(a));
}
__device__ __forceinline__ void ldsm_x2t(u32 &r0, u32 &r1, u32 a) {
    asm volatile("ldmatrix.sync.aligned.m8n8.x2.trans.shared.b16 {%0,%1},[%2];"
                 : "=r"(r0), "=r"(r1) : "r"(a));
}
__device__ __forceinline__ void mma_bf16(float* d, const u32* a, u32 b0, u32 b1) {
    asm volatile("mma.sync.aligned.m16n8k16.row.col.f32.bf16.bf16.f32 "
                 "{%0,%1,%2,%3},{%4,%5,%6,%7},{%8,%9},{%0,%1,%2,%3};"
                 : "+f"(d[0]), "+f"(d[1]), "+f"(d[2]), "+f"(d[3])
                 : "r"(a[0]), "r"(a[1]), "r"(a[2]), "r"(a[3]), "r"(b0), "r"(b1));
}

// ---------------- scratch ----------------
__device__ __align__(16) float g_h0[HSZ];
__device__ __align__(16) float g_h1[HSZ];
__device__ __align__(16) float g_fy [BATCH*WID*NN*MD*2];   // y-half 0 partial
__device__ __align__(16) float g_fy2[BATCH*WID*NN*MD*2];   // y-half 1 partial
__device__ __align__(16) float g_fxy[BATCH*WID*MD*MD*2];
__device__ __align__(16) float g_ymix[BATCH*WID*MD*MD*2];
__device__ __align__(16) float g_gx [BATCH*WID*NN*MD*2];
__device__ __align__(16) float g_swt[4*256*4096*2];
__device__ __align__(16) __nv_bfloat16 g_Thi[32*256];
__device__ __align__(16) __nv_bfloat16 g_Tlo[32*256];
__device__ __align__(16) float2 g_tab[NN];

__device__ __forceinline__ float* hbuf(int s) { return s ? g_h1 : g_h0; }

__global__ void init_tab_kernel() {
    int m = threadIdx.x;
    double a = (2.0 * 3.14159265358979323846 * (double)m) / 256.0;
    g_tab[m] = make_float2((float)cos(a), (float)sin(a));
}

// T matrix: T[2k2][y]=cos(2pi k2 y/256), T[2k2+1][y]=-sin(...)
__global__ void init_T_kernel() {
    int idx = blockIdx.x * 256 + threadIdx.x;
    int row = idx >> 8, y = idx & 255;
    int k2 = row >> 1;
    double a = (2.0 * 3.14159265358979323846 * (double)(k2 * y)) / 256.0;
    float val = (row & 1) ? (float)(-sin(a)) : (float)cos(a);
    __nv_bfloat16 h = __float2bfloat16(val);
    g_Thi[idx] = h;
    g_Tlo[idx] = __float2bfloat16(val - __bfloat162float(h));
}

// ---------------- sw transpose ----------------
__global__ __launch_bounds__(256) void sw_transpose(const float* __restrict__ s0,
                                                    const float* __restrict__ s1,
                                                    const float* __restrict__ s2,
                                                    const float* __restrict__ s3) {
    __shared__ float2 tile[32][65];
    int tid = threadIdx.x;
    int l   = blockIdx.x >> 9;
    int iot = (blockIdx.x >> 3) & 63;
    int mt  = blockIdx.x & 7;
    const float* sw = (l == 0) ? s0 : (l == 1) ? s1 : (l == 2) ? s2 : s3;
    int io0 = iot * 64, m0 = mt * 32;
    int c = tid & 31, r = tid >> 5;
#pragma unroll
    for (int rr = r; rr < 64; rr += 8)
        tile[c][rr] = reinterpret_cast<const float2*>(sw)[(size_t)(io0 + rr) * 256 + m0 + c];
    __syncthreads();
    int c2 = tid & 63, mr = tid >> 6;
    float2* dst = reinterpret_cast<float2*>(g_swt);
#pragma unroll
    for (int mm = mr; mm < 32; mm += 4)
        dst[((size_t)(l * 256 + m0 + mm) * 4096) + io0 + c2] = tile[mm][c2];
}

// ---------------- smem layout (split-y: 128 y per CTA) ----------------
#define BP 136               // B pitch (bf16 elems): 128 data + 8 pad (272 B rows)
#define AP 104               // A pitch
#define CV_BHI  0            // bf16 [96][136]  26112 B (rows 0-63 res/h, 64-95 T)
#define CV_BLO  26112
#define CV_AHI  52224        // bf16 [64][104]  13312 B
#define CV_ALO  65536
#define CV_CBS  78848        // f32 [64]
#define CV_HW   79104        // f32 [64]
#define CV_HB   79360
#define CONV_SMEM 79376

#define F0_XS   52224        // f32 [384]
#define F0_WS   53760        // f32 [192]
#define F0_BS   54528        // f32 [64]
#define F0_SMEM 54784
#define SRH 132              // fp32 res pitch (head layer)

// ---------------- Fy partial via tensor cores (8 warps, K=128 y-half) ----------------
__device__ __forceinline__ void fy_mma(char* smb, int b, int xx, int yh, int w, int lane) {
    const __nv_bfloat16* bhi = reinterpret_cast<const __nv_bfloat16*>(smb + CV_BHI);
    const __nv_bfloat16* blo = reinterpret_cast<const __nv_bfloat16*>(smb + CV_BLO);
    int orow = (w & 3) * 16;
    int cgrp = (w >> 2) * 16;          // 2 groups of 16 T-rows
    int mat = lane >> 3;
    u32 arow_off = (u32)((orow + ((mat & 1) << 3) + (lane & 7)) * BP + ((mat >> 1) << 3)) * 2;
    u32 aoff_hi = sptr(bhi) + arow_off;
    u32 aoff_lo = sptr(blo) + arow_off;
    int bl = lane & 15;
    u32 b0_off = (u32)((64 + cgrp + (bl & 7)) * BP + ((bl >> 3) << 3)) * 2;
    u32 b1_off = b0_off + (u32)(8 * BP) * 2;
    u32 b0_hi = sptr(bhi) + b0_off, b0_lo = sptr(blo) + b0_off;
    u32 b1_hi = sptr(bhi) + b1_off, b1_lo = sptr(blo) + b1_off;

    float d0[4] = {0.f, 0.f, 0.f, 0.f};
    float d1[4] = {0.f, 0.f, 0.f, 0.f};
#pragma unroll
    for (int kk = 0; kk < 8; kk++) {
        u32 Ah[4], Al[4], Bh0, Bh1, Bl0, Bl1, Ch0, Ch1, Cl0, Cl1;
        ldsm_x4(Ah, aoff_hi + kk * 32);
        ldsm_x4(Al, aoff_lo + kk * 32);
        ldsm_x2(Bh0, Bh1, b0_hi + kk * 32);
        ldsm_x2(Bl0, Bl1, b0_lo + kk * 32);
        ldsm_x2(Ch0, Ch1, b1_hi + kk * 32);
        ldsm_x2(Cl0, Cl1, b1_lo + kk * 32);
        mma_bf16(d0, Ah, Bh0, Bh1);
        mma_bf16(d0, Ah, Bl0, Bl1);
        mma_bf16(d0, Al, Bh0, Bh1);
        mma_bf16(d1, Ah, Ch0, Ch1);
        mma_bf16(d1, Ah, Cl0, Cl1);
        mma_bf16(d1, Al, Ch0, Ch1);
    }
    float* fybuf = yh ? g_fy2 : g_fy;
    int rowt = lane >> 2;
    int c0 = cgrp + (lane & 3) * 2;
    float* dst = fybuf + ((size_t)(b * 64 + orow + rowt) * 256 + xx) * 32;
    *reinterpret_cast<float2*>(dst + c0)                 = make_float2(d0[0], d0[1]);
    *reinterpret_cast<float2*>(dst + 8 * 8192 + c0)      = make_float2(d0[2], d0[3]);
    *reinterpret_cast<float2*>(dst + c0 + 8)             = make_float2(d1[0], d1[1]);
    *reinterpret_cast<float2*>(dst + 8 * 8192 + c0 + 8)  = make_float2(d1[2], d1[3]);
}

// ---------------- T staging (rows 64-95, y-half slice) ----------------
__device__ __forceinline__ void stage_T(char* smb, int yh, int tid) {
    __nv_bfloat16* bhi = reinterpret_cast<__nv_bfloat16*>(smb + CV_BHI);
    __nv_bfloat16* blo = reinterpret_cast<__nv_bfloat16*>(smb + CV_BLO);
#pragma unroll
    for (int t = 0; t < 2; t++) {
        int vidx = tid + t * 256;       // 512 16B chunks per array
        int r = vidx >> 4, c = vidx & 15;
        *reinterpret_cast<ulonglong2*>(bhi + (64 + r) * BP + c * 8) =
            *reinterpret_cast<const ulonglong2*>(g_Thi + r * 256 + yh * 128 + c * 8);
        *reinterpret_cast<ulonglong2*>(blo + (64 + r) * BP + c * 8) =
            *reinterpret_cast<const ulonglong2*>(g_Tlo + r * 256 + yh * 128 + c * 8);
    }
}

// ---------------- lift + Fy (split-y) ----------------
__global__ __launch_bounds__(256, 2) void fc0_fy(const float* __restrict__ x,
                                                 const float* __restrict__ w,
                                                 const float* __restrict__ bias) {
    extern __shared__ float smf[];
    char* smb = reinterpret_cast<char*>(smf);
    __nv_bfloat16* bhi = reinterpret_cast<__nv_bfloat16*>(smb + CV_BHI);
    __nv_bfloat16* blo = reinterpret_cast<__nv_bfloat16*>(smb + CV_BLO);
    float* xs = reinterpret_cast<float*>(smb + F0_XS);
    float* ws = reinterpret_cast<float*>(smb + F0_WS);
    float* bs = reinterpret_cast<float*>(smb + F0_BS);
    int tid = threadIdx.x;
    int b = blockIdx.x >> 9, xx = (blockIdx.x >> 1) & 255, yh = blockIdx.x & 1;

    for (int idx = tid; idx < 384; idx += 256) {
        int c = idx >> 7, y = idx & 127;
        xs[idx] = x[(((size_t)(b * 3 + c) * 256 + xx) << 8) + yh * 128 + y];
    }
    if (tid < 192) ws[tid] = w[tid];
    if (tid < 64)  bs[tid] = bias[tid];
    stage_T(smb, yh, tid);
    __syncthreads();

    int o = tid >> 2, q = tid & 3;
    float w0 = ws[o * 3], w1 = ws[o * 3 + 1], w2v = ws[o * 3 + 2], bb = bs[o];
    float* hdst = g_h0 + ((size_t)(b * 64 + o) << 16) + xx * 256 + yh * 128;
#pragma unroll
    for (int j = 0; j < 16; j++) {
        int y = q * 2 + 8 * j;
        float v0 = fmaf(w0, xs[y],     fmaf(w1, xs[128 + y],     fmaf(w2v, xs[256 + y],     bb)));
        float v1 = fmaf(w0, xs[y + 1], fmaf(w1, xs[128 + y + 1], fmaf(w2v, xs[256 + y + 1], bb)));
        *reinterpret_cast<float2*>(hdst + y) = make_float2(v0, v1);
        __nv_bfloat162 h2 = __floats2bfloat162_rn(v0, v1);
        __nv_bfloat162 l2 = __floats2bfloat162_rn(v0 - __low2float(h2), v1 - __high2float(h2));
        *reinterpret_cast<__nv_bfloat162*>(bhi + o * BP + y) = h2;
        *reinterpret_cast<__nv_bfloat162*>(blo + o * BP + y) = l2;
    }
    __syncthreads();
    fy_mma(smb, b, xx, yh, tid >> 5, tid & 31);
}

// ---------------- stage 2a: x-forward DFT (sums the two Fy halves) ----------------
__global__ __launch_bounds__(256) void dftx_fwd() {
    __shared__ float2 Fs[NN * MD];
    __shared__ float2 tb[NN];
    __shared__ float4 red[256];
    int tid = threadIdx.x;
    int bc = blockIdx.x;
    const float4* s1 = reinterpret_cast<const float4*>(g_fy  + (size_t)bc * NN * 32);
    const float4* s2 = reinterpret_cast<const float4*>(g_fy2 + (size_t)bc * NN * 32);
    float4* fd = reinterpret_cast<float4*>(Fs);
#pragma unroll
    for (int j = 0; j < 8; j++) {
        float4 a = s1[tid + j * 256], c = s2[tid + j * 256];
        fd[tid + j * 256] = make_float4(a.x + c.x, a.y + c.y, a.z + c.z, a.w + c.w);
    }
    tb[tid] = g_tab[tid];
    __syncthreads();
    int g = tid >> 7;
    int tt = tid & 127;
    int k1 = tt >> 3;
    int k2p = tt & 7;
    float re0 = 0.f, im0 = 0.f, re1 = 0.f, im1 = 0.f;
    int m = (g * 128 * k1) & 255;
    int x0 = g * 128;
#pragma unroll 8
    for (int xi = 0; xi < 128; xi++) {
        float4 F = *reinterpret_cast<const float4*>(&Fs[(x0 + xi) * 16 + k2p * 2]);
        float2 e = tb[m];
        m = (m + k1) & 255;
        re0 = fmaf(F.x, e.x, re0); re0 = fmaf(F.y, e.y, re0);
        im0 = fmaf(F.y, e.x, im0); im0 = fmaf(-F.x, e.y, im0);
        re1 = fmaf(F.z, e.x, re1); re1 = fmaf(F.w, e.y, re1);
        im1 = fmaf(F.w, e.x, im1); im1 = fmaf(-F.z, e.y, im1);
    }
    red[tid] = make_float4(re0, im0, re1, im1);
    __syncthreads();
    if (tid < 128) {
        float4 a = red[tid], c = red[tid + 128];
        *reinterpret_cast<float4*>(g_fxy + (size_t)bc * 512 + k1 * 32 + k2p * 4) =
            make_float4(a.x + c.x, a.y + c.y, a.z + c.z, a.w + c.w);
    }
}

// ---------------- stage 2b: per-mode channel mix ----------------
__global__ __launch_bounds__(256) void mode_mix(int l) {
    __shared__ float WsR[WID * WID];
    __shared__ float WsI[WID * WID];
    __shared__ float2 Xs[BATCH * WID];
    int tid  = threadIdx.x;
    int mode = blockIdx.x;
    const float2* wsrc = reinterpret_cast<const float2*>(g_swt) +
                         (size_t)(l * 256 + mode) * 4096;
    for (int idx = tid; idx < WID * WID; idx += 256) {
        float2 v = wsrc[idx];
        WsR[idx] = v.x;
        WsI[idx] = v.y;
    }
    for (int idx = tid; idx < BATCH * WID; idx += 256) {
        const float* p = g_fxy + ((size_t)idx * 256 + mode) * 2;
        Xs[idx] = make_float2(p[0], p[1]);
    }
    __syncthreads();
    int o = tid & 63, bg = tid >> 6;
    const float sc = 1.0f / 65536.0f;
#pragma unroll
    for (int t = 0; t < 4; t++) {
        int b = bg * 4 + t;
        float aR = 0.f, aI = 0.f;
#pragma unroll 8
        for (int i = 0; i < 64; i++) {
            float2 X = Xs[b * 64 + i];
            float wr = WsR[i * 64 + o], wi = WsI[i * 64 + o];
            aR = fmaf(X.x, wr, aR); aR = fmaf(-X.y, wi, aR);
            aI = fmaf(X.x, wi, aI); aI = fmaf( X.y, wr, aI);
        }
        float* p = g_ymix + ((size_t)(b * 64 + o) * 256 + mode) * 2;
        p[0] = aR * sc;
        p[1] = aI * sc;
    }
}

// ---------------- stage 2c: x-inverse DFT ----------------
__global__ __launch_bounds__(256) void dftx_inv() {
    __shared__ float2 Ys[256];
    __shared__ float2 tb[NN];
    int tid = threadIdx.x;
    int bo  = blockIdx.x;
    Ys[tid] = reinterpret_cast<const float2*>(g_ymix)[(size_t)bo * 256 + tid];
    tb[tid] = g_tab[tid];
    __syncthreads();
    int x = tid;
    float2 acc[16];
#pragma unroll
    for (int k2 = 0; k2 < 16; k2++) acc[k2] = make_float2(0.f, 0.f);
    int m = 0;
#pragma unroll
    for (int k1 = 0; k1 < 16; k1++) {
        float2 e = tb[m];
        m = (m + x) & 255;
#pragma unroll
        for (int k2 = 0; k2 < 16; k2++) {
            float2 Yv = Ys[k1 * 16 + k2];
            acc[k2].x = fmaf(Yv.x, e.x, acc[k2].x); acc[k2].x = fmaf(-Yv.y, e.y, acc[k2].x);
            acc[k2].y = fmaf(Yv.x, e.y, acc[k2].y); acc[k2].y = fmaf( Yv.y, e.x, acc[k2].y);
        }
    }
    float* dst = g_gx + ((size_t)bo * 256 + x) * 32;
#pragma unroll
    for (int k2 = 0; k2 < 16; k2++) { dst[2 * k2] = acc[k2].x; dst[2 * k2 + 1] = acc[k2].y; }
}

// ---------------- stage 3: GEMM [W|G] x [h;T] + GELU (+Fy / +head), split-y ----------------
__global__ __launch_bounds__(256, 2) void conv_mma(int src, int dst,
                                                   const float* __restrict__ cw,
                                                   const float* __restrict__ cb,
                                                   int hasSpec, int doFy, int doHead,
                                                   const float* __restrict__ hw,
                                                   const float* __restrict__ hb,
                                                   float* __restrict__ out) {
    extern __shared__ float smf[];
    char* smb = reinterpret_cast<char*>(smf);
    __nv_bfloat16* bhi = reinterpret_cast<__nv_bfloat16*>(smb + CV_BHI);
    __nv_bfloat16* blo = reinterpret_cast<__nv_bfloat16*>(smb + CV_BLO);
    __nv_bfloat16* ahi = reinterpret_cast<__nv_bfloat16*>(smb + CV_AHI);
    __nv_bfloat16* alo = reinterpret_cast<__nv_bfloat16*>(smb + CV_ALO);
    float* cbs  = reinterpret_cast<float*>(smb + CV_CBS);

    const float* __restrict__ hin = hbuf(src);
    float* __restrict__ hout = hbuf(dst);
    int tid = threadIdx.x;
    int b = blockIdx.x >> 9, xx = (blockIdx.x >> 1) & 255, yh = blockIdx.x & 1;

    // ---- h staging: 64 x 128 fp32 -> bf16 hi/lo ----
    const float* hbase = hin + ((size_t)b * 64 * 256 + xx) * 256 + yh * 128;
#pragma unroll
    for (int j = 0; j < 8; j++) {
        int slot = tid + j * 256;
        int i = slot >> 5, c4 = (slot & 31) * 4;
        float4 v = *reinterpret_cast<const float4*>(hbase + (size_t)i * 65536 + c4);
        __nv_bfloat162 h01 = __floats2bfloat162_rn(v.x, v.y);
        __nv_bfloat162 h23 = __floats2bfloat162_rn(v.z, v.w);
        __nv_bfloat162 l01 = __floats2bfloat162_rn(v.x - __low2float(h01), v.y - __high2float(h01));
        __nv_bfloat162 l23 = __floats2bfloat162_rn(v.z - __low2float(h23), v.w - __high2float(h23));
        *reinterpret_cast<__nv_bfloat162*>(bhi + i * BP + c4)     = h01;
        *reinterpret_cast<__nv_bfloat162*>(bhi + i * BP + c4 + 2) = h23;
        *reinterpret_cast<__nv_bfloat162*>(blo + i * BP + c4)     = l01;
        *reinterpret_cast<__nv_bfloat162*>(blo + i * BP + c4 + 2) = l23;
    }
    stage_T(smb, yh, tid);
    // ---- W staging ----
#pragma unroll
    for (int t = 0; t < 8; t++) {
        int pidx = tid * 8 + t;                   // 2048 pairs
        int o = pidx >> 5, ip = (pidx & 31) * 2;
        float2 wv = *reinterpret_cast<const float2*>(cw + o * 64 + ip);
        __nv_bfloat162 h2 = __floats2bfloat162_rn(wv.x, wv.y);
        __nv_bfloat162 l2 = __floats2bfloat162_rn(wv.x - __low2float(h2), wv.y - __high2float(h2));
        *reinterpret_cast<__nv_bfloat162*>(ahi + o * AP + ip) = h2;
        *reinterpret_cast<__nv_bfloat162*>(alo + o * AP + ip) = l2;
    }
    // ---- G staging ----
    if (hasSpec) {
#pragma unroll
        for (int t = 0; t < 4; t++) {
            int cidx = tid * 4 + t;               // 1024 complex (o,k2)
            int o = cidx >> 4, k2 = cidx & 15;
            float2 g = *reinterpret_cast<const float2*>(
                g_gx + (((size_t)(b * 64 + o) * 256 + xx) << 5) + 2 * k2);
            float dd = (k2 > 0) ? 2.f : 1.f;
            float gre = dd * g.x, gim = dd * g.y;
            __nv_bfloat162 h2 = __floats2bfloat162_rn(gre, gim);
            __nv_bfloat162 l2 = __floats2bfloat162_rn(gre - __low2float(h2), gim - __high2float(h2));
            *reinterpret_cast<__nv_bfloat162*>(ahi + o * AP + 64 + 2 * k2) = h2;
            *reinterpret_cast<__nv_bfloat162*>(alo + o * AP + 64 + 2 * k2) = l2;
        }
    }
    if (tid < 64) cbs[tid] = cb[tid];
    if (doHead) {
        if (tid < 64) reinterpret_cast<float*>(smb + CV_HW)[tid] = hw[tid];
        if (tid == 0) reinterpret_cast<float*>(smb + CV_HB)[0] = hb[0];
    }
    __syncthreads();

    int w    = tid >> 5, lane = tid & 31;
    int obase = (w & 1) * 32;            // 2 o-groups of 32
    int ygrp  = w >> 1;                  // 4 y-groups of 32 (local)
    int rowt = lane >> 2, col = lane & 3;

    float d[2][4][4];
#pragma unroll
    for (int a = 0; a < 2; a++)
#pragma unroll
        for (int j = 0; j < 4; j++)
#pragma unroll
            for (int c = 0; c < 4; c++) d[a][j][c] = 0.f;

    {
        int mat = lane >> 3;
        int arow = obase + ((mat & 1) << 3) + (lane & 7);
        int kh = (mat >> 1) << 3;
        u32 a0_hi = sptr(ahi) + (u32)(arow * AP + kh) * 2;
        u32 a0_lo = sptr(alo) + (u32)(arow * AP + kh) * 2;
        u32 a1_hi = a0_hi + 16 * AP * 2;
        u32 a1_lo = a0_lo + 16 * AP * 2;
        int brow = lane & 15;
        u32 bbase_hi = sptr(bhi) + (u32)(brow * BP) * 2;
        u32 bbase_lo = sptr(blo) + (u32)(brow * BP) * 2;
        int kLim = hasSpec ? 6 : 4;
#pragma unroll 2
        for (int k = 0; k < kLim; k++) {
            u32 Ah0[4], Al0[4], Ah1[4], Al1[4];
            ldsm_x4(Ah0, a0_hi + k * 32);
            ldsm_x4(Al0, a0_lo + k * 32);
            ldsm_x4(Ah1, a1_hi + k * 32);
            ldsm_x4(Al1, a1_lo + k * 32);
#pragma unroll
            for (int j = 0; j < 4; j++) {
                u32 off = (u32)(k * 16 * BP + ygrp * 32 + j * 8) * 2;
                u32 bh0, bh1, bl0, bl1;
                ldsm_x2t(bh0, bh1, bbase_hi + off);
                ldsm_x2t(bl0, bl1, bbase_lo + off);
                mma_bf16(d[0][j], Ah0, bh0, bh1);
                mma_bf16(d[0][j], Ah0, bl0, bl1);
                mma_bf16(d[0][j], Al0, bh0, bh1);
                mma_bf16(d[1][j], Ah1, bh0, bh1);
                mma_bf16(d[1][j], Ah1, bl0, bl1);
                mma_bf16(d[1][j], Al1, bh0, bh1);
            }
        }
    }

    // ---- epilogue: bias + exact GELU ----
    __syncthreads();
    float* res = smf;   // fp32 [64][SRH] (head layer only; overlaps B region)
#pragma unroll
    for (int a = 0; a < 2; a++) {
#pragma unroll
        for (int j = 0; j < 4; j++) {
            int y0 = ygrp * 32 + j * 8 + col * 2;   // local y
#pragma unroll
            for (int r = 0; r < 2; r++) {
                int o = obase + a * 16 + rowt + 8 * r;
                float bias = cbs[o];
                float p = d[a][j][2 * r] + bias;
                float q = d[a][j][2 * r + 1] + bias;
                float gp = 0.5f * p * (1.0f + erff(p * 0.70710678118654752f));
                float gq = 0.5f * q * (1.0f + erff(q * 0.70710678118654752f));
                if (doFy) {
                    __nv_bfloat162 h2 = __floats2bfloat162_rn(gp, gq);
                    __nv_bfloat162 l2 = __floats2bfloat162_rn(gp - __low2float(h2), gq - __high2float(h2));
                    *reinterpret_cast<__nv_bfloat162*>(bhi + o * BP + y0) = h2;
                    *reinterpret_cast<__nv_bfloat162*>(blo + o * BP + y0) = l2;
                }
                if (doHead)
                    *reinterpret_cast<float2*>(res + o * SRH + y0) = make_float2(gp, gq);
                if (!doHead)
                    *reinterpret_cast<float2*>(hout + ((size_t)(b * 64 + o) << 16) +
                                               xx * 256 + yh * 128 + y0) = make_float2(gp, gq);
            }
        }
    }

    if (doFy) {
        __syncthreads();
        fy_mma(smb, b, xx, yh, w, lane);
    }
    if (doHead) {
        __syncthreads();
        if (tid < 128) {
            const float* hwS = reinterpret_cast<const float*>(smb + CV_HW);
            float a = reinterpret_cast<const float*>(smb + CV_HB)[0];
            int y = tid;
#pragma unroll 16
            for (int f = 0; f < 64; f++) a = fmaf(res[f * SRH + y], hwS[f], a);
            out[(size_t)b * 65536 + xx * 256 + yh * 128 + y] = a;
        }
    }
}

// ---------------- launch ----------------
extern "C" void kernel_launch(void* const* d_in, const int* in_sizes, int n_in,
                              void* d_out, int out_size) {
    const float* x     = (const float*)d_in[0];
    const float* fc0_w = (const float*)d_in[1];
    const float* fc0_b = (const float*)d_in[2];
    const float* sw[4] = {(const float*)d_in[3], (const float*)d_in[4],
                          (const float*)d_in[5], (const float*)d_in[6]};
    const float* cw[4] = {(const float*)d_in[7], (const float*)d_in[9],
                          (const float*)d_in[11], (const float*)d_in[13]};
    const float* cb[4] = {(const float*)d_in[8], (const float*)d_in[10],
                          (const float*)d_in[12], (const float*)d_in[14]};
    const float* fc1_w = (const float*)d_in[15];
    const float* fc1_b = (const float*)d_in[16];
    const float* fc2_w = (const float*)d_in[17];
    const float* fc2_b = (const float*)d_in[18];
    float* out = (float*)d_out;

    cudaFuncSetAttribute(conv_mma, cudaFuncAttributeMaxDynamicSharedMemorySize, CONV_SMEM);
    cudaFuncSetAttribute(fc0_fy,   cudaFuncAttributeMaxDynamicSharedMemorySize, F0_SMEM);

    init_tab_kernel<<<1, 256>>>();
    init_T_kernel<<<32, 256>>>();
    sw_transpose<<<2048, 256>>>(sw[0], sw[1], sw[2], sw[3]);
    fc0_fy<<<8192, 256, F0_SMEM>>>(x, fc0_w, fc0_b);

    int src = 0;
    for (int l = 0; l < 4; l++) {
        dftx_fwd<<<1024, 256>>>();
        mode_mix<<<256, 256>>>(l);
        dftx_inv<<<1024, 256>>>();
        int doFy = (l < 3) ? 1 : 0;
        conv_mma<<<8192, 256, CONV_SMEM>>>(src, 1 - src, cw[l], cb[l],
                                           1, doFy, 0, nullptr, nullptr, nullptr);
        src = 1 - src;
    }
    conv_mma<<<8192, 256, CONV_SMEM>>>(src, src, fc1_w, fc1_b,
                                       0, 0, 1, fc2_w, fc2_b, out);
}

// round 14
// speedup vs baseline: 1.0509x; 1.0509x over previous
#include <cuda_runtime.h>
#include <cuda_bf16.h>
#include <stdint.h>
#include <math.h>

#define NN    256
#define BATCH 16
#define WID   64
#define MD    16
#define HSZ   (BATCH*WID*NN*NN)

typedef unsigned long long u64;
typedef unsigned int u32;

// ---------------- tensor-core helpers ----------------
__device__ __forceinline__ u32 sptr(const void* p) {
    return (u32)__cvta_generic_to_shared(p);
}
__device__ __forceinline__ void ldsm_x4(u32* r, u32 a) {
    asm volatile("ldmatrix.sync.aligned.m8n8.x4.shared.b16 {%0,%1,%2,%3},[%4];"
                 : "=r"(r[0]), "=r"(r[1]), "=r"(r[2]), "=r"(r[3]) : "r"(a));
}
__device__ __forceinline__ void ldsm_x2(u32 &r0, u32 &r1, u32 a) {
    asm volatile("ldmatrix.sync.aligned.m8n8.x2.shared.b16 {%0,%1},[%2];"
                 : "=r"(r0), "=r"(r1) : "r"(a));
}
__device__ __forceinline__ void ldsm_x2t(u32 &r0, u32 &r1, u32 a) {
    asm volatile("ldmatrix.sync.aligned.m8n8.x2.trans.shared.b16 {%0,%1},[%2];"
                 : "=r"(r0), "=r"(r1) : "r"(a));
}
__device__ __forceinline__ void mma_bf16(float* d, const u32* a, u32 b0, u32 b1) {
    asm volatile("mma.sync.aligned.m16n8k16.row.col.f32.bf16.bf16.f32 "
                 "{%0,%1,%2,%3},{%4,%5,%6,%7},{%8,%9},{%0,%1,%2,%3};"
                 : "+f"(d[0]), "+f"(d[1]), "+f"(d[2]), "+f"(d[3])
                 : "r"(a[0]), "r"(a[1]), "r"(a[2]), "r"(a[3]), "r"(b0), "r"(b1));
}
__device__ __forceinline__ u32 bf2u(__nv_bfloat162 v) { return *reinterpret_cast<u32*>(&v); }

// ---------------- scratch ----------------
__device__ __align__(16) float g_h0[HSZ];
__device__ __align__(16) float g_h1[HSZ];
__device__ __align__(16) float g_fy [BATCH*WID*NN*MD*2];
__device__ __align__(16) float g_fy2[BATCH*WID*NN*MD*2];
__device__ __align__(16) float g_fxy[BATCH*WID*MD*MD*2];
__device__ __align__(16) float g_ymix[BATCH*WID*MD*MD*2];
__device__ __align__(16) float g_gx [BATCH*WID*NN*MD*2];
__device__ __align__(16) float g_swt[4*256*4096*2];
__device__ __align__(16) __nv_bfloat16 g_Thi[32*256];
__device__ __align__(16) __nv_bfloat16 g_Tlo[32*256];
__device__ __align__(16) float2 g_tab[NN];

__device__ __forceinline__ float* hbuf(int s) { return s ? g_h1 : g_h0; }

__global__ void init_tab_kernel() {
    int m = threadIdx.x;
    double a = (2.0 * 3.14159265358979323846 * (double)m) / 256.0;
    g_tab[m] = make_float2((float)cos(a), (float)sin(a));
}

__global__ void init_T_kernel() {
    int idx = blockIdx.x * 256 + threadIdx.x;
    int row = idx >> 8, y = idx & 255;
    int k2 = row >> 1;
    double a = (2.0 * 3.14159265358979323846 * (double)(k2 * y)) / 256.0;
    float val = (row & 1) ? (float)(-sin(a)) : (float)cos(a);
    __nv_bfloat16 h = __float2bfloat16(val);
    g_Thi[idx] = h;
    g_Tlo[idx] = __float2bfloat16(val - __bfloat162float(h));
}

// ---------------- sw transpose ----------------
__global__ __launch_bounds__(256) void sw_transpose(const float* __restrict__ s0,
                                                    const float* __restrict__ s1,
                                                    const float* __restrict__ s2,
                                                    const float* __restrict__ s3) {
    __shared__ float2 tile[32][65];
    int tid = threadIdx.x;
    int l   = blockIdx.x >> 9;
    int iot = (blockIdx.x >> 3) & 63;
    int mt  = blockIdx.x & 7;
    const float* sw = (l == 0) ? s0 : (l == 1) ? s1 : (l == 2) ? s2 : s3;
    int io0 = iot * 64, m0 = mt * 32;
    int c = tid & 31, r = tid >> 5;
#pragma unroll
    for (int rr = r; rr < 64; rr += 8)
        tile[c][rr] = reinterpret_cast<const float2*>(sw)[(size_t)(io0 + rr) * 256 + m0 + c];
    __syncthreads();
    int c2 = tid & 63, mr = tid >> 6;
    float2* dst = reinterpret_cast<float2*>(g_swt);
#pragma unroll
    for (int mm = mr; mm < 32; mm += 4)
        dst[((size_t)(l * 256 + m0 + mm) * 4096) + io0 + c2] = tile[mm][c2];
}

// ---------------- smem layout (split-y: 128 y per CTA) ----------------
#define BP 136
#define AP 104
#define CV_BHI  0
#define CV_BLO  26112
#define CV_AHI  52224
#define CV_ALO  65536
#define CV_CBS  78848
#define CV_HW   79104
#define CV_HB   79360
#define CONV_SMEM 79376

#define F0_XS   52224
#define F0_WS   53760
#define F0_BS   54528
#define F0_SMEM 54784
#define SRH 132

// ---------------- Fy partial via tensor cores (split accumulators) ----------------
__device__ __forceinline__ void fy_mma(char* smb, int b, int xx, int yh, int w, int lane) {
    const __nv_bfloat16* bhi = reinterpret_cast<const __nv_bfloat16*>(smb + CV_BHI);
    const __nv_bfloat16* blo = reinterpret_cast<const __nv_bfloat16*>(smb + CV_BLO);
    int orow = (w & 3) * 16;
    int cgrp = (w >> 2) * 16;
    int mat = lane >> 3;
    u32 arow_off = (u32)((orow + ((mat & 1) << 3) + (lane & 7)) * BP + ((mat >> 1) << 3)) * 2;
    u32 aoff_hi = sptr(bhi) + arow_off;
    u32 aoff_lo = sptr(blo) + arow_off;
    int bl = lane & 15;
    u32 b0_off = (u32)((64 + cgrp + (bl & 7)) * BP + ((bl >> 3) << 3)) * 2;
    u32 b1_off = b0_off + (u32)(8 * BP) * 2;
    u32 b0_hi = sptr(bhi) + b0_off, b0_lo = sptr(blo) + b0_off;
    u32 b1_hi = sptr(bhi) + b1_off, b1_lo = sptr(blo) + b1_off;

    float d0a[4] = {0,0,0,0}, d0b[4] = {0,0,0,0};
    float d1a[4] = {0,0,0,0}, d1b[4] = {0,0,0,0};
#pragma unroll
    for (int kk = 0; kk < 8; kk++) {
        u32 Ah[4], Al[4], Bh0, Bh1, Bl0, Bl1, Ch0, Ch1, Cl0, Cl1;
        ldsm_x4(Ah, aoff_hi + kk * 32);
        ldsm_x4(Al, aoff_lo + kk * 32);
        ldsm_x2(Bh0, Bh1, b0_hi + kk * 32);
        ldsm_x2(Bl0, Bl1, b0_lo + kk * 32);
        ldsm_x2(Ch0, Ch1, b1_hi + kk * 32);
        ldsm_x2(Cl0, Cl1, b1_lo + kk * 32);
        mma_bf16(d0a, Ah, Bh0, Bh1);
        mma_bf16(d0b, Ah, Bl0, Bl1);
        mma_bf16(d0b, Al, Bh0, Bh1);
        mma_bf16(d1a, Ah, Ch0, Ch1);
        mma_bf16(d1b, Ah, Cl0, Cl1);
        mma_bf16(d1b, Al, Ch0, Ch1);
    }
    float* fybuf = yh ? g_fy2 : g_fy;
    int rowt = lane >> 2;
    int c0 = cgrp + (lane & 3) * 2;
    float* dst = fybuf + ((size_t)(b * 64 + orow + rowt) * 256 + xx) * 32;
    *reinterpret_cast<float2*>(dst + c0)                = make_float2(d0a[0] + d0b[0], d0a[1] + d0b[1]);
    *reinterpret_cast<float2*>(dst + 8 * 8192 + c0)     = make_float2(d0a[2] + d0b[2], d0a[3] + d0b[3]);
    *reinterpret_cast<float2*>(dst + c0 + 8)            = make_float2(d1a[0] + d1b[0], d1a[1] + d1b[1]);
    *reinterpret_cast<float2*>(dst + 8 * 8192 + c0 + 8) = make_float2(d1a[2] + d1b[2], d1a[3] + d1b[3]);
}

// ---------------- T staging ----------------
__device__ __forceinline__ void stage_T(char* smb, int yh, int tid) {
    __nv_bfloat16* bhi = reinterpret_cast<__nv_bfloat16*>(smb + CV_BHI);
    __nv_bfloat16* blo = reinterpret_cast<__nv_bfloat16*>(smb + CV_BLO);
#pragma unroll
    for (int t = 0; t < 2; t++) {
        int vidx = tid + t * 256;
        int r = vidx >> 4, c = vidx & 15;
        *reinterpret_cast<ulonglong2*>(bhi + (64 + r) * BP + c * 8) =
            *reinterpret_cast<const ulonglong2*>(g_Thi + r * 256 + yh * 128 + c * 8);
        *reinterpret_cast<ulonglong2*>(blo + (64 + r) * BP + c * 8) =
            *reinterpret_cast<const ulonglong2*>(g_Tlo + r * 256 + yh * 128 + c * 8);
    }
}

// ---------------- lift + Fy (split-y) ----------------
__global__ __launch_bounds__(256, 2) void fc0_fy(const float* __restrict__ x,
                                                 const float* __restrict__ w,
                                                 const float* __restrict__ bias) {
    extern __shared__ float smf[];
    char* smb = reinterpret_cast<char*>(smf);
    __nv_bfloat16* bhi = reinterpret_cast<__nv_bfloat16*>(smb + CV_BHI);
    __nv_bfloat16* blo = reinterpret_cast<__nv_bfloat16*>(smb + CV_BLO);
    float* xs = reinterpret_cast<float*>(smb + F0_XS);
    float* ws = reinterpret_cast<float*>(smb + F0_WS);
    float* bs = reinterpret_cast<float*>(smb + F0_BS);
    int tid = threadIdx.x;
    int b = blockIdx.x >> 9, xx = (blockIdx.x >> 1) & 255, yh = blockIdx.x & 1;

    for (int idx = tid; idx < 384; idx += 256) {
        int c = idx >> 7, y = idx & 127;
        xs[idx] = x[(((size_t)(b * 3 + c) * 256 + xx) << 8) + yh * 128 + y];
    }
    if (tid < 192) ws[tid] = w[tid];
    if (tid < 64)  bs[tid] = bias[tid];
    stage_T(smb, yh, tid);
    __syncthreads();

    int o = tid >> 2, q = tid & 3;
    float w0 = ws[o * 3], w1 = ws[o * 3 + 1], w2v = ws[o * 3 + 2], bb = bs[o];
    float* hdst = g_h0 + ((size_t)(b * 64 + o) << 16) + xx * 256 + yh * 128;
#pragma unroll
    for (int j = 0; j < 8; j++) {
        int y = q * 4 + 16 * j;
        float v0 = fmaf(w0, xs[y],     fmaf(w1, xs[128 + y],     fmaf(w2v, xs[256 + y],     bb)));
        float v1 = fmaf(w0, xs[y + 1], fmaf(w1, xs[128 + y + 1], fmaf(w2v, xs[256 + y + 1], bb)));
        float v2 = fmaf(w0, xs[y + 2], fmaf(w1, xs[128 + y + 2], fmaf(w2v, xs[256 + y + 2], bb)));
        float v3 = fmaf(w0, xs[y + 3], fmaf(w1, xs[128 + y + 3], fmaf(w2v, xs[256 + y + 3], bb)));
        *reinterpret_cast<float4*>(hdst + y) = make_float4(v0, v1, v2, v3);
        __nv_bfloat162 h01 = __floats2bfloat162_rn(v0, v1);
        __nv_bfloat162 h23 = __floats2bfloat162_rn(v2, v3);
        __nv_bfloat162 l01 = __floats2bfloat162_rn(v0 - __low2float(h01), v1 - __high2float(h01));
        __nv_bfloat162 l23 = __floats2bfloat162_rn(v2 - __low2float(h23), v3 - __high2float(h23));
        *reinterpret_cast<uint2*>(bhi + o * BP + y) = make_uint2(bf2u(h01), bf2u(h23));
        *reinterpret_cast<uint2*>(blo + o * BP + y) = make_uint2(bf2u(l01), bf2u(l23));
    }
    __syncthreads();
    fy_mma(smb, b, xx, yh, tid >> 5, tid & 31);
}

// ---------------- stage 2a: x-forward DFT ----------------
__global__ __launch_bounds__(256) void dftx_fwd() {
    __shared__ float2 Fs[NN * MD];
    __shared__ float2 tb[NN];
    __shared__ float4 red[256];
    int tid = threadIdx.x;
    int bc = blockIdx.x;
    const float4* s1 = reinterpret_cast<const float4*>(g_fy  + (size_t)bc * NN * 32);
    const float4* s2 = reinterpret_cast<const float4*>(g_fy2 + (size_t)bc * NN * 32);
    float4* fd = reinterpret_cast<float4*>(Fs);
#pragma unroll
    for (int j = 0; j < 8; j++) {
        float4 a = s1[tid + j * 256], c = s2[tid + j * 256];
        fd[tid + j * 256] = make_float4(a.x + c.x, a.y + c.y, a.z + c.z, a.w + c.w);
    }
    tb[tid] = g_tab[tid];
    __syncthreads();
    int g = tid >> 7;
    int tt = tid & 127;
    int k1 = tt >> 3;
    int k2p = tt & 7;
    float re0 = 0.f, im0 = 0.f, re1 = 0.f, im1 = 0.f;
    int m = (g * 128 * k1) & 255;
    int x0 = g * 128;
#pragma unroll 8
    for (int xi = 0; xi < 128; xi++) {
        float4 F = *reinterpret_cast<const float4*>(&Fs[(x0 + xi) * 16 + k2p * 2]);
        float2 e = tb[m];
        m = (m + k1) & 255;
        re0 = fmaf(F.x, e.x, re0); re0 = fmaf(F.y, e.y, re0);
        im0 = fmaf(F.y, e.x, im0); im0 = fmaf(-F.x, e.y, im0);
        re1 = fmaf(F.z, e.x, re1); re1 = fmaf(F.w, e.y, re1);
        im1 = fmaf(F.w, e.x, im1); im1 = fmaf(-F.z, e.y, im1);
    }
    red[tid] = make_float4(re0, im0, re1, im1);
    __syncthreads();
    if (tid < 128) {
        float4 a = red[tid], c = red[tid + 128];
        *reinterpret_cast<float4*>(g_fxy + (size_t)bc * 512 + k1 * 32 + k2p * 4) =
            make_float4(a.x + c.x, a.y + c.y, a.z + c.z, a.w + c.w);
    }
}

// ---------------- stage 2b: per-mode channel mix ----------------
__global__ __launch_bounds__(256) void mode_mix(int l) {
    __shared__ float WsR[WID * WID];
    __shared__ float WsI[WID * WID];
    __shared__ float2 Xs[BATCH * WID];
    int tid  = threadIdx.x;
    int mode = blockIdx.x;
    const float2* wsrc = reinterpret_cast<const float2*>(g_swt) +
                         (size_t)(l * 256 + mode) * 4096;
    for (int idx = tid; idx < WID * WID; idx += 256) {
        float2 v = wsrc[idx];
        WsR[idx] = v.x;
        WsI[idx] = v.y;
    }
    for (int idx = tid; idx < BATCH * WID; idx += 256) {
        const float* p = g_fxy + ((size_t)idx * 256 + mode) * 2;
        Xs[idx] = make_float2(p[0], p[1]);
    }
    __syncthreads();
    int o = tid & 63, bg = tid >> 6;
    const float sc = 1.0f / 65536.0f;
#pragma unroll
    for (int t = 0; t < 4; t++) {
        int b = bg * 4 + t;
        float aR = 0.f, aI = 0.f;
#pragma unroll 8
        for (int i = 0; i < 64; i++) {
            float2 X = Xs[b * 64 + i];
            float wr = WsR[i * 64 + o], wi = WsI[i * 64 + o];
            aR = fmaf(X.x, wr, aR); aR = fmaf(-X.y, wi, aR);
            aI = fmaf(X.x, wi, aI); aI = fmaf( X.y, wr, aI);
        }
        float* p = g_ymix + ((size_t)(b * 64 + o) * 256 + mode) * 2;
        p[0] = aR * sc;
        p[1] = aI * sc;
    }
}

// ---------------- stage 2c: x-inverse DFT ----------------
__global__ __launch_bounds__(256) void dftx_inv() {
    __shared__ float2 Ys[256];
    __shared__ float2 tb[NN];
    int tid = threadIdx.x;
    int bo  = blockIdx.x;
    Ys[tid] = reinterpret_cast<const float2*>(g_ymix)[(size_t)bo * 256 + tid];
    tb[tid] = g_tab[tid];
    __syncthreads();
    int x = tid;
    float2 acc[16];
#pragma unroll
    for (int k2 = 0; k2 < 16; k2++) acc[k2] = make_float2(0.f, 0.f);
    int m = 0;
#pragma unroll
    for (int k1 = 0; k1 < 16; k1++) {
        float2 e = tb[m];
        m = (m + x) & 255;
#pragma unroll
        for (int k2 = 0; k2 < 16; k2++) {
            float2 Yv = Ys[k1 * 16 + k2];
            acc[k2].x = fmaf(Yv.x, e.x, acc[k2].x); acc[k2].x = fmaf(-Yv.y, e.y, acc[k2].x);
            acc[k2].y = fmaf(Yv.x, e.y, acc[k2].y); acc[k2].y = fmaf( Yv.y, e.x, acc[k2].y);
        }
    }
    float* dst = g_gx + ((size_t)bo * 256 + x) * 32;
#pragma unroll
    for (int k2 = 0; k2 < 16; k2++) { dst[2 * k2] = acc[k2].x; dst[2 * k2 + 1] = acc[k2].y; }
}

// ---------------- stage 3: GEMM [W|G] x [h;T] + GELU (+Fy / +head), split-y ----------------
__global__ __launch_bounds__(256, 2) void conv_mma(int src, int dst,
                                                   const float* __restrict__ cw,
                                                   const float* __restrict__ cb,
                                                   int hasSpec, int doFy, int doHead,
                                                   const float* __restrict__ hw,
                                                   const float* __restrict__ hb,
                                                   float* __restrict__ out) {
    extern __shared__ float smf[];
    char* smb = reinterpret_cast<char*>(smf);
    __nv_bfloat16* bhi = reinterpret_cast<__nv_bfloat16*>(smb + CV_BHI);
    __nv_bfloat16* blo = reinterpret_cast<__nv_bfloat16*>(smb + CV_BLO);
    __nv_bfloat16* ahi = reinterpret_cast<__nv_bfloat16*>(smb + CV_AHI);
    __nv_bfloat16* alo = reinterpret_cast<__nv_bfloat16*>(smb + CV_ALO);
    float* cbs  = reinterpret_cast<float*>(smb + CV_CBS);

    const float* __restrict__ hin = hbuf(src);
    float* __restrict__ hout = hbuf(dst);
    int tid = threadIdx.x;
    int b = blockIdx.x >> 9, xx = (blockIdx.x >> 1) & 255, yh = blockIdx.x & 1;

    // ---- h staging: 64 x 128 fp32 -> bf16 hi/lo (packed 8B stores) ----
    const float* hbase = hin + ((size_t)b * 64 * 256 + xx) * 256 + yh * 128;
#pragma unroll
    for (int j = 0; j < 8; j++) {
        int slot = tid + j * 256;
        int i = slot >> 5, c4 = (slot & 31) * 4;
        float4 v = *reinterpret_cast<const float4*>(hbase + (size_t)i * 65536 + c4);
        __nv_bfloat162 h01 = __floats2bfloat162_rn(v.x, v.y);
        __nv_bfloat162 h23 = __floats2bfloat162_rn(v.z, v.w);
        __nv_bfloat162 l01 = __floats2bfloat162_rn(v.x - __low2float(h01), v.y - __high2float(h01));
        __nv_bfloat162 l23 = __floats2bfloat162_rn(v.z - __low2float(h23), v.w - __high2float(h23));
        *reinterpret_cast<uint2*>(bhi + i * BP + c4) = make_uint2(bf2u(h01), bf2u(h23));
        *reinterpret_cast<uint2*>(blo + i * BP + c4) = make_uint2(bf2u(l01), bf2u(l23));
    }
    stage_T(smb, yh, tid);
    // ---- W staging (packed 8B stores) ----
#pragma unroll
    for (int t = 0; t < 4; t++) {
        int qidx = tid * 4 + t;                   // 1024 quads
        int o = qidx >> 4, ip = (qidx & 15) * 4;
        float4 wv = *reinterpret_cast<const float4*>(cw + o * 64 + ip);
        __nv_bfloat162 h01 = __floats2bfloat162_rn(wv.x, wv.y);
        __nv_bfloat162 h23 = __floats2bfloat162_rn(wv.z, wv.w);
        __nv_bfloat162 l01 = __floats2bfloat162_rn(wv.x - __low2float(h01), wv.y - __high2float(h01));
        __nv_bfloat162 l23 = __floats2bfloat162_rn(wv.z - __low2float(h23), wv.w - __high2float(h23));
        *reinterpret_cast<uint2*>(ahi + o * AP + ip) = make_uint2(bf2u(h01), bf2u(h23));
        *reinterpret_cast<uint2*>(alo + o * AP + ip) = make_uint2(bf2u(l01), bf2u(l23));
    }
    // ---- G staging (packed 8B stores; k2-pairs) ----
    if (hasSpec) {
#pragma unroll
        for (int t = 0; t < 2; t++) {
            int cidx = tid * 2 + t;               // 512 k2-pairs
            int o = cidx >> 3, k2p = (cidx & 7) * 2;
            float4 g = *reinterpret_cast<const float4*>(
                g_gx + (((size_t)(b * 64 + o) * 256 + xx) << 5) + 2 * k2p);
            float d0 = (k2p > 0) ? 2.f : 1.f;
            float a0 = d0 * g.x, a1 = d0 * g.y, a2 = 2.f * g.z, a3 = 2.f * g.w;
            __nv_bfloat162 h01 = __floats2bfloat162_rn(a0, a1);
            __nv_bfloat162 h23 = __floats2bfloat162_rn(a2, a3);
            __nv_bfloat162 l01 = __floats2bfloat162_rn(a0 - __low2float(h01), a1 - __high2float(h01));
            __nv_bfloat162 l23 = __floats2bfloat162_rn(a2 - __low2float(h23), a3 - __high2float(h23));
            *reinterpret_cast<uint2*>(ahi + o * AP + 64 + 2 * k2p) = make_uint2(bf2u(h01), bf2u(h23));
            *reinterpret_cast<uint2*>(alo + o * AP + 64 + 2 * k2p) = make_uint2(bf2u(l01), bf2u(l23));
        }
    }
    if (tid < 64) cbs[tid] = cb[tid];
    if (doHead) {
        if (tid < 64) reinterpret_cast<float*>(smb + CV_HW)[tid] = hw[tid];
        if (tid == 0) reinterpret_cast<float*>(smb + CV_HB)[0] = hb[0];
    }
    __syncthreads();

    int w    = tid >> 5, lane = tid & 31;
    int obase = (w & 1) * 32;
    int ygrp  = w >> 1;
    int rowt = lane >> 2, col = lane & 3;

    float dh[2][4][4], dc[2][4][4];
#pragma unroll
    for (int a = 0; a < 2; a++)
#pragma unroll
        for (int j = 0; j < 4; j++)
#pragma unroll
            for (int c = 0; c < 4; c++) { dh[a][j][c] = 0.f; dc[a][j][c] = 0.f; }

    {
        int mat = lane >> 3;
        int arow = obase + ((mat & 1) << 3) + (lane & 7);
        int kh = (mat >> 1) << 3;
        u32 a0_hi = sptr(ahi) + (u32)(arow * AP + kh) * 2;
        u32 a0_lo = sptr(alo) + (u32)(arow * AP + kh) * 2;
        u32 a1_hi = a0_hi + 16 * AP * 2;
        u32 a1_lo = a0_lo + 16 * AP * 2;
        int brow = lane & 15;
        u32 bbase_hi = sptr(bhi) + (u32)(brow * BP) * 2;
        u32 bbase_lo = sptr(blo) + (u32)(brow * BP) * 2;
        int kLim = hasSpec ? 6 : 4;
#pragma unroll 2
        for (int k = 0; k < kLim; k++) {
            u32 Ah0[4], Al0[4], Ah1[4], Al1[4];
            ldsm_x4(Ah0, a0_hi + k * 32);
            ldsm_x4(Al0, a0_lo + k * 32);
            ldsm_x4(Ah1, a1_hi + k * 32);
            ldsm_x4(Al1, a1_lo + k * 32);
#pragma unroll
            for (int j = 0; j < 4; j++) {
                u32 off = (u32)(k * 16 * BP + ygrp * 32 + j * 8) * 2;
                u32 bh0, bh1, bl0, bl1;
                ldsm_x2t(bh0, bh1, bbase_hi + off);
                ldsm_x2t(bl0, bl1, bbase_lo + off);
                mma_bf16(dh[0][j], Ah0, bh0, bh1);
                mma_bf16(dc[0][j], Ah0, bl0, bl1);
                mma_bf16(dc[0][j], Al0, bh0, bh1);
                mma_bf16(dh[1][j], Ah1, bh0, bh1);
                mma_bf16(dc[1][j], Ah1, bl0, bl1);
                mma_bf16(dc[1][j], Al1, bh0, bh1);
            }
        }
    }

    // ---- epilogue: merge + bias + exact GELU ----
    __syncthreads();
    float* res = smf;
#pragma unroll
    for (int a = 0; a < 2; a++) {
#pragma unroll
        for (int j = 0; j < 4; j++) {
            int y0 = ygrp * 32 + j * 8 + col * 2;
#pragma unroll
            for (int r = 0; r < 2; r++) {
                int o = obase + a * 16 + rowt + 8 * r;
                float bias = cbs[o];
                float p = dh[a][j][2 * r]     + dc[a][j][2 * r]     + bias;
                float q = dh[a][j][2 * r + 1] + dc[a][j][2 * r + 1] + bias;
                float gp = 0.5f * p * (1.0f + erff(p * 0.70710678118654752f));
                float gq = 0.5f * q * (1.0f + erff(q * 0.70710678118654752f));
                if (doFy) {
                    __nv_bfloat162 h2 = __floats2bfloat162_rn(gp, gq);
                    __nv_bfloat162 l2 = __floats2bfloat162_rn(gp - __low2float(h2), gq - __high2float(h2));
                    *reinterpret_cast<__nv_bfloat162*>(bhi + o * BP + y0) = h2;
                    *reinterpret_cast<__nv_bfloat162*>(blo + o * BP + y0) = l2;
                }
                if (doHead)
                    *reinterpret_cast<float2*>(res + o * SRH + y0) = make_float2(gp, gq);
                if (!doHead)
                    *reinterpret_cast<float2*>(hout + ((size_t)(b * 64 + o) << 16) +
                                               xx * 256 + yh * 128 + y0) = make_float2(gp, gq);
            }
        }
    }

    if (doFy) {
        __syncthreads();
        fy_mma(smb, b, xx, yh, w, lane);
    }
    if (doHead) {
        __syncthreads();
        if (tid < 128) {
            const float* hwS = reinterpret_cast<const float*>(smb + CV_HW);
            float a = reinterpret_cast<const float*>(smb + CV_HB)[0];
            int y = tid;
#pragma unroll 16
            for (int f = 0; f < 64; f++) a = fmaf(res[f * SRH + y], hwS[f], a);
            out[(size_t)b * 65536 + xx * 256 + yh * 128 + y] = a;
        }
    }
}

// ---------------- launch ----------------
extern "C" void kernel_launch(void* const* d_in, const int* in_sizes, int n_in,
                              void* d_out, int out_size) {
    const float* x     = (const float*)d_in[0];
    const float* fc0_w = (const float*)d_in[1];
    const float* fc0_b = (const float*)d_in[2];
    const float* sw[4] = {(const float*)d_in[3], (const float*)d_in[4],
                          (const float*)d_in[5], (const float*)d_in[6]};
    const float* cw[4] = {(const float*)d_in[7], (const float*)d_in[9],
                          (const float*)d_in[11], (const float*)d_in[13]};
    const float* cb[4] = {(const float*)d_in[8], (const float*)d_in[10],
                          (const float*)d_in[12], (const float*)d_in[14]};
    const float* fc1_w = (const float*)d_in[15];
    const float* fc1_b = (const float*)d_in[16];
    const float* fc2_w = (const float*)d_in[17];
    const float* fc2_b = (const float*)d_in[18];
    float* out = (float*)d_out;

    cudaFuncSetAttribute(conv_mma, cudaFuncAttributeMaxDynamicSharedMemorySize, CONV_SMEM);
    cudaFuncSetAttribute(fc0_fy,   cudaFuncAttributeMaxDynamicSharedMemorySize, F0_SMEM);

    init_tab_kernel<<<1, 256>>>();
    init_T_kernel<<<32, 256>>>();
    sw_transpose<<<2048, 256>>>(sw[0], sw[1], sw[2], sw[3]);
    fc0_fy<<<8192, 256, F0_SMEM>>>(x, fc0_w, fc0_b);

    int src = 0;
    for (int l = 0; l < 4; l++) {
        dftx_fwd<<<1024, 256>>>();
        mode_mix<<<256, 256>>>(l);
        dftx_inv<<<1024, 256>>>();
        int doFy = (l < 3) ? 1 : 0;
        conv_mma<<<8192, 256, CONV_SMEM>>>(src, 1 - src, cw[l], cb[l],
                                           1, doFy, 0, nullptr, nullptr, nullptr);
        src = 1 - src;
    }
    conv_mma<<<8192, 256, CONV_SMEM>>>(src, src, fc1_w, fc1_b,
                                       0, 0, 1, fc2_w, fc2_b, out);
}

// round 15
// speedup vs baseline: 1.0629x; 1.0114x over previous
#include <cuda_runtime.h>
#include <cuda_bf16.h>
#include <stdint.h>
#include <math.h>

#define NN    256
#define BATCH 16
#define WID   64
#define MD    16
#define HSZ   (BATCH*WID*NN*NN)

typedef unsigned long long u64;
typedef unsigned int u32;

// ---------------- tensor-core helpers ----------------
__device__ __forceinline__ u32 sptr(const void* p) {
    return (u32)__cvta_generic_to_shared(p);
}
__device__ __forceinline__ void ldsm_x4(u32* r, u32 a) {
    asm volatile("ldmatrix.sync.aligned.m8n8.x4.shared.b16 {%0,%1,%2,%3},[%4];"
                 : "=r"(r[0]), "=r"(r[1]), "=r"(r[2]), "=r"(r[3]) : "r"(a));
}
__device__ __forceinline__ void ldsm_x4t(u32* r, u32 a) {
    asm volatile("ldmatrix.sync.aligned.m8n8.x4.trans.shared.b16 {%0,%1,%2,%3},[%4];"
                 : "=r"(r[0]), "=r"(r[1]), "=r"(r[2]), "=r"(r[3]) : "r"(a));
}
__device__ __forceinline__ void mma_bf16(float* d, const u32* a, u32 b0, u32 b1) {
    asm volatile("mma.sync.aligned.m16n8k16.row.col.f32.bf16.bf16.f32 "
                 "{%0,%1,%2,%3},{%4,%5,%6,%7},{%8,%9},{%0,%1,%2,%3};"
                 : "+f"(d[0]), "+f"(d[1]), "+f"(d[2]), "+f"(d[3])
                 : "r"(a[0]), "r"(a[1]), "r"(a[2]), "r"(a[3]), "r"(b0), "r"(b1));
}
__device__ __forceinline__ u32 bf2u(__nv_bfloat162 v) { return *reinterpret_cast<u32*>(&v); }

// ---------------- scratch ----------------
__device__ __align__(16) float g_h0[HSZ];
__device__ __align__(16) float g_h1[HSZ];
__device__ __align__(16) float g_fy [BATCH*WID*NN*MD*2];
__device__ __align__(16) float g_fy2[BATCH*WID*NN*MD*2];
__device__ __align__(16) float g_fxy[BATCH*WID*MD*MD*2];
__device__ __align__(16) float g_ymix[BATCH*WID*MD*MD*2];
__device__ __align__(16) float g_gx [BATCH*WID*NN*MD*2];
__device__ __align__(16) float g_swt[4*256*4096*2];
__device__ __align__(16) __nv_bfloat16 g_Thi[32*256];
__device__ __align__(16) __nv_bfloat16 g_Tlo[32*256];
__device__ __align__(16) float2 g_tab[NN];

__device__ __forceinline__ float* hbuf(int s) { return s ? g_h1 : g_h0; }

__global__ void init_tab_kernel() {
    int m = threadIdx.x;
    double a = (2.0 * 3.14159265358979323846 * (double)m) / 256.0;
    g_tab[m] = make_float2((float)cos(a), (float)sin(a));
}

__global__ void init_T_kernel() {
    int idx = blockIdx.x * 256 + threadIdx.x;
    int row = idx >> 8, y = idx & 255;
    int k2 = row >> 1;
    double a = (2.0 * 3.14159265358979323846 * (double)(k2 * y)) / 256.0;
    float val = (row & 1) ? (float)(-sin(a)) : (float)cos(a);
    __nv_bfloat16 h = __float2bfloat16(val);
    g_Thi[idx] = h;
    g_Tlo[idx] = __float2bfloat16(val - __bfloat162float(h));
}

// ---------------- sw transpose ----------------
__global__ __launch_bounds__(256) void sw_transpose(const float* __restrict__ s0,
                                                    const float* __restrict__ s1,
                                                    const float* __restrict__ s2,
                                                    const float* __restrict__ s3) {
    __shared__ float2 tile[32][65];
    int tid = threadIdx.x;
    int l   = blockIdx.x >> 9;
    int iot = (blockIdx.x >> 3) & 63;
    int mt  = blockIdx.x & 7;
    const float* sw = (l == 0) ? s0 : (l == 1) ? s1 : (l == 2) ? s2 : s3;
    int io0 = iot * 64, m0 = mt * 32;
    int c = tid & 31, r = tid >> 5;
#pragma unroll
    for (int rr = r; rr < 64; rr += 8)
        tile[c][rr] = reinterpret_cast<const float2*>(sw)[(size_t)(io0 + rr) * 256 + m0 + c];
    __syncthreads();
    int c2 = tid & 63, mr = tid >> 6;
    float2* dst = reinterpret_cast<float2*>(g_swt);
#pragma unroll
    for (int mm = mr; mm < 32; mm += 4)
        dst[((size_t)(l * 256 + m0 + mm) * 4096) + io0 + c2] = tile[mm][c2];
}

// ---------------- smem layout (split-y: 128 y per CTA) ----------------
#define BP 136
#define AP 104
#define CV_BHI  0
#define CV_BLO  26112
#define CV_AHI  52224
#define CV_ALO  65536
#define CV_CBS  78848
#define CV_HW   79104
#define CV_HB   79360
#define CONV_SMEM 79376

#define F0_XS   52224
#define F0_WS   53760
#define F0_BS   54528
#define F0_SMEM 54784
#define SRH 132

// ---------------- Fy partial via tensor cores ----------------
__device__ __forceinline__ void fy_mma(char* smb, int b, int xx, int yh, int w, int lane) {
    const __nv_bfloat16* bhi = reinterpret_cast<const __nv_bfloat16*>(smb + CV_BHI);
    const __nv_bfloat16* blo = reinterpret_cast<const __nv_bfloat16*>(smb + CV_BLO);
    int orow = (w & 3) * 16;
    int cgrp = (w >> 2) * 16;
    int mat = lane >> 3;
    u32 arow_off = (u32)((orow + ((mat & 1) << 3) + (lane & 7)) * BP + ((mat >> 1) << 3)) * 2;
    u32 aoff_hi = sptr(bhi) + arow_off;
    u32 aoff_lo = sptr(blo) + arow_off;
    // x4 non-trans B: t0-15 -> rows cgrp..+8 (k-halves), t16-31 -> rows +8..+16
    u32 brow_off = (u32)((64 + cgrp + (lane & 7) + ((lane >> 4) << 3)) * BP +
                         (((lane >> 3) & 1) << 3)) * 2;
    u32 boff_hi = sptr(bhi) + brow_off;
    u32 boff_lo = sptr(blo) + brow_off;

    float d0a[4] = {0,0,0,0}, d0b[4] = {0,0,0,0};
    float d1a[4] = {0,0,0,0}, d1b[4] = {0,0,0,0};
#pragma unroll
    for (int kk = 0; kk < 8; kk++) {
        u32 Ah[4], Al[4], Bh[4], Bl[4];
        ldsm_x4(Ah, aoff_hi + kk * 32);
        ldsm_x4(Al, aoff_lo + kk * 32);
        ldsm_x4(Bh, boff_hi + kk * 32);
        ldsm_x4(Bl, boff_lo + kk * 32);
        mma_bf16(d0a, Ah, Bh[0], Bh[1]);
        mma_bf16(d0b, Ah, Bl[0], Bl[1]);
        mma_bf16(d0b, Al, Bh[0], Bh[1]);
        mma_bf16(d1a, Ah, Bh[2], Bh[3]);
        mma_bf16(d1b, Ah, Bl[2], Bl[3]);
        mma_bf16(d1b, Al, Bh[2], Bh[3]);
    }
    float* fybuf = yh ? g_fy2 : g_fy;
    int rowt = lane >> 2;
    int c0 = cgrp + (lane & 3) * 2;
    float* dst = fybuf + ((size_t)(b * 64 + orow + rowt) * 256 + xx) * 32;
    *reinterpret_cast<float2*>(dst + c0)                = make_float2(d0a[0] + d0b[0], d0a[1] + d0b[1]);
    *reinterpret_cast<float2*>(dst + 8 * 8192 + c0)     = make_float2(d0a[2] + d0b[2], d0a[3] + d0b[3]);
    *reinterpret_cast<float2*>(dst + c0 + 8)            = make_float2(d1a[0] + d1b[0], d1a[1] + d1b[1]);
    *reinterpret_cast<float2*>(dst + 8 * 8192 + c0 + 8) = make_float2(d1a[2] + d1b[2], d1a[3] + d1b[3]);
}

// ---------------- T staging ----------------
__device__ __forceinline__ void stage_T(char* smb, int yh, int tid) {
    __nv_bfloat16* bhi = reinterpret_cast<__nv_bfloat16*>(smb + CV_BHI);
    __nv_bfloat16* blo = reinterpret_cast<__nv_bfloat16*>(smb + CV_BLO);
#pragma unroll
    for (int t = 0; t < 2; t++) {
        int vidx = tid + t * 256;
        int r = vidx >> 4, c = vidx & 15;
        *reinterpret_cast<ulonglong2*>(bhi + (64 + r) * BP + c * 8) =
            *reinterpret_cast<const ulonglong2*>(g_Thi + r * 256 + yh * 128 + c * 8);
        *reinterpret_cast<ulonglong2*>(blo + (64 + r) * BP + c * 8) =
            *reinterpret_cast<const ulonglong2*>(g_Tlo + r * 256 + yh * 128 + c * 8);
    }
}

// ---------------- lift + Fy (split-y) ----------------
__global__ __launch_bounds__(256, 2) void fc0_fy(const float* __restrict__ x,
                                                 const float* __restrict__ w,
                                                 const float* __restrict__ bias) {
    extern __shared__ float smf[];
    char* smb = reinterpret_cast<char*>(smf);
    __nv_bfloat16* bhi = reinterpret_cast<__nv_bfloat16*>(smb + CV_BHI);
    __nv_bfloat16* blo = reinterpret_cast<__nv_bfloat16*>(smb + CV_BLO);
    float* xs = reinterpret_cast<float*>(smb + F0_XS);
    float* ws = reinterpret_cast<float*>(smb + F0_WS);
    float* bs = reinterpret_cast<float*>(smb + F0_BS);
    int tid = threadIdx.x;
    int b = blockIdx.x >> 9, xx = (blockIdx.x >> 1) & 255, yh = blockIdx.x & 1;

    for (int idx = tid; idx < 384; idx += 256) {
        int c = idx >> 7, y = idx & 127;
        xs[idx] = x[(((size_t)(b * 3 + c) * 256 + xx) << 8) + yh * 128 + y];
    }
    if (tid < 192) ws[tid] = w[tid];
    if (tid < 64)  bs[tid] = bias[tid];
    stage_T(smb, yh, tid);
    __syncthreads();

    int o = tid >> 2, q = tid & 3;
    float w0 = ws[o * 3], w1 = ws[o * 3 + 1], w2v = ws[o * 3 + 2], bb = bs[o];
    float* hdst = g_h0 + ((size_t)(b * 64 + o) << 16) + xx * 256 + yh * 128;
#pragma unroll
    for (int j = 0; j < 8; j++) {
        int y = q * 4 + 16 * j;
        float v0 = fmaf(w0, xs[y],     fmaf(w1, xs[128 + y],     fmaf(w2v, xs[256 + y],     bb)));
        float v1 = fmaf(w0, xs[y + 1], fmaf(w1, xs[128 + y + 1], fmaf(w2v, xs[256 + y + 1], bb)));
        float v2 = fmaf(w0, xs[y + 2], fmaf(w1, xs[128 + y + 2], fmaf(w2v, xs[256 + y + 2], bb)));
        float v3 = fmaf(w0, xs[y + 3], fmaf(w1, xs[128 + y + 3], fmaf(w2v, xs[256 + y + 3], bb)));
        *reinterpret_cast<float4*>(hdst + y) = make_float4(v0, v1, v2, v3);
        __nv_bfloat162 h01 = __floats2bfloat162_rn(v0, v1);
        __nv_bfloat162 h23 = __floats2bfloat162_rn(v2, v3);
        __nv_bfloat162 l01 = __floats2bfloat162_rn(v0 - __low2float(h01), v1 - __high2float(h01));
        __nv_bfloat162 l23 = __floats2bfloat162_rn(v2 - __low2float(h23), v3 - __high2float(h23));
        *reinterpret_cast<uint2*>(bhi + o * BP + y) = make_uint2(bf2u(h01), bf2u(h23));
        *reinterpret_cast<uint2*>(blo + o * BP + y) = make_uint2(bf2u(l01), bf2u(l23));
    }
    __syncthreads();
    fy_mma(smb, b, xx, yh, tid >> 5, tid & 31);
}

// ---------------- stage 2a: x-forward DFT ----------------
__global__ __launch_bounds__(256) void dftx_fwd() {
    __shared__ float2 Fs[NN * MD];
    __shared__ float2 tb[NN];
    __shared__ float4 red[256];
    int tid = threadIdx.x;
    int bc = blockIdx.x;
    const float4* s1 = reinterpret_cast<const float4*>(g_fy  + (size_t)bc * NN * 32);
    const float4* s2 = reinterpret_cast<const float4*>(g_fy2 + (size_t)bc * NN * 32);
    float4* fd = reinterpret_cast<float4*>(Fs);
#pragma unroll
    for (int j = 0; j < 8; j++) {
        float4 a = s1[tid + j * 256], c = s2[tid + j * 256];
        fd[tid + j * 256] = make_float4(a.x + c.x, a.y + c.y, a.z + c.z, a.w + c.w);
    }
    tb[tid] = g_tab[tid];
    __syncthreads();
    int g = tid >> 7;
    int tt = tid & 127;
    int k1 = tt >> 3;
    int k2p = tt & 7;
    float re0 = 0.f, im0 = 0.f, re1 = 0.f, im1 = 0.f;
    int m = (g * 128 * k1) & 255;
    int x0 = g * 128;
#pragma unroll 8
    for (int xi = 0; xi < 128; xi++) {
        float4 F = *reinterpret_cast<const float4*>(&Fs[(x0 + xi) * 16 + k2p * 2]);
        float2 e = tb[m];
        m = (m + k1) & 255;
        re0 = fmaf(F.x, e.x, re0); re0 = fmaf(F.y, e.y, re0);
        im0 = fmaf(F.y, e.x, im0); im0 = fmaf(-F.x, e.y, im0);
        re1 = fmaf(F.z, e.x, re1); re1 = fmaf(F.w, e.y, re1);
        im1 = fmaf(F.w, e.x, im1); im1 = fmaf(-F.z, e.y, im1);
    }
    red[tid] = make_float4(re0, im0, re1, im1);
    __syncthreads();
    if (tid < 128) {
        float4 a = red[tid], c = red[tid + 128];
        *reinterpret_cast<float4*>(g_fxy + (size_t)bc * 512 + k1 * 32 + k2p * 4) =
            make_float4(a.x + c.x, a.y + c.y, a.z + c.z, a.w + c.w);
    }
}

// ---------------- stage 2b: per-mode channel mix ----------------
__global__ __launch_bounds__(256) void mode_mix(int l) {
    __shared__ float WsR[WID * WID];
    __shared__ float WsI[WID * WID];
    __shared__ float2 Xs[BATCH * WID];
    int tid  = threadIdx.x;
    int mode = blockIdx.x;
    const float2* wsrc = reinterpret_cast<const float2*>(g_swt) +
                         (size_t)(l * 256 + mode) * 4096;
    for (int idx = tid; idx < WID * WID; idx += 256) {
        float2 v = wsrc[idx];
        WsR[idx] = v.x;
        WsI[idx] = v.y;
    }
    for (int idx = tid; idx < BATCH * WID; idx += 256) {
        const float* p = g_fxy + ((size_t)idx * 256 + mode) * 2;
        Xs[idx] = make_float2(p[0], p[1]);
    }
    __syncthreads();
    int o = tid & 63, bg = tid >> 6;
    const float sc = 1.0f / 65536.0f;
#pragma unroll
    for (int t = 0; t < 4; t++) {
        int b = bg * 4 + t;
        float aR = 0.f, aI = 0.f;
#pragma unroll 8
        for (int i = 0; i < 64; i++) {
            float2 X = Xs[b * 64 + i];
            float wr = WsR[i * 64 + o], wi = WsI[i * 64 + o];
            aR = fmaf(X.x, wr, aR); aR = fmaf(-X.y, wi, aR);
            aI = fmaf(X.x, wi, aI); aI = fmaf( X.y, wr, aI);
        }
        float* p = g_ymix + ((size_t)(b * 64 + o) * 256 + mode) * 2;
        p[0] = aR * sc;
        p[1] = aI * sc;
    }
}

// ---------------- stage 2c: x-inverse DFT ----------------
__global__ __launch_bounds__(256) void dftx_inv() {
    __shared__ float2 Ys[256];
    __shared__ float2 tb[NN];
    int tid = threadIdx.x;
    int bo  = blockIdx.x;
    Ys[tid] = reinterpret_cast<const float2*>(g_ymix)[(size_t)bo * 256 + tid];
    tb[tid] = g_tab[tid];
    __syncthreads();
    int x = tid;
    float2 acc[16];
#pragma unroll
    for (int k2 = 0; k2 < 16; k2++) acc[k2] = make_float2(0.f, 0.f);
    int m = 0;
#pragma unroll
    for (int k1 = 0; k1 < 16; k1++) {
        float2 e = tb[m];
        m = (m + x) & 255;
#pragma unroll
        for (int k2 = 0; k2 < 16; k2++) {
            float2 Yv = Ys[k1 * 16 + k2];
            acc[k2].x = fmaf(Yv.x, e.x, acc[k2].x); acc[k2].x = fmaf(-Yv.y, e.y, acc[k2].x);
            acc[k2].y = fmaf(Yv.x, e.y, acc[k2].y); acc[k2].y = fmaf( Yv.y, e.x, acc[k2].y);
        }
    }
    float* dst = g_gx + ((size_t)bo * 256 + x) * 32;
#pragma unroll
    for (int k2 = 0; k2 < 16; k2++) { dst[2 * k2] = acc[k2].x; dst[2 * k2 + 1] = acc[k2].y; }
}

// ---------------- stage 3: GEMM [W|G] x [h;T] + GELU (+Fy / +head), split-y ----------------
__global__ __launch_bounds__(256, 2) void conv_mma(int src, int dst,
                                                   const float* __restrict__ cw,
                                                   const float* __restrict__ cb,
                                                   int hasSpec, int doFy, int doHead,
                                                   const float* __restrict__ hw,
                                                   const float* __restrict__ hb,
                                                   float* __restrict__ out) {
    extern __shared__ float smf[];
    char* smb = reinterpret_cast<char*>(smf);
    __nv_bfloat16* bhi = reinterpret_cast<__nv_bfloat16*>(smb + CV_BHI);
    __nv_bfloat16* blo = reinterpret_cast<__nv_bfloat16*>(smb + CV_BLO);
    __nv_bfloat16* ahi = reinterpret_cast<__nv_bfloat16*>(smb + CV_AHI);
    __nv_bfloat16* alo = reinterpret_cast<__nv_bfloat16*>(smb + CV_ALO);
    float* cbs  = reinterpret_cast<float*>(smb + CV_CBS);

    const float* __restrict__ hin = hbuf(src);
    float* __restrict__ hout = hbuf(dst);
    int tid = threadIdx.x;
    int b = blockIdx.x >> 9, xx = (blockIdx.x >> 1) & 255, yh = blockIdx.x & 1;

    // ---- h staging ----
    const float* hbase = hin + ((size_t)b * 64 * 256 + xx) * 256 + yh * 128;
#pragma unroll
    for (int j = 0; j < 8; j++) {
        int slot = tid + j * 256;
        int i = slot >> 5, c4 = (slot & 31) * 4;
        float4 v = *reinterpret_cast<const float4*>(hbase + (size_t)i * 65536 + c4);
        __nv_bfloat162 h01 = __floats2bfloat162_rn(v.x, v.y);
        __nv_bfloat162 h23 = __floats2bfloat162_rn(v.z, v.w);
        __nv_bfloat162 l01 = __floats2bfloat162_rn(v.x - __low2float(h01), v.y - __high2float(h01));
        __nv_bfloat162 l23 = __floats2bfloat162_rn(v.z - __low2float(h23), v.w - __high2float(h23));
        *reinterpret_cast<uint2*>(bhi + i * BP + c4) = make_uint2(bf2u(h01), bf2u(h23));
        *reinterpret_cast<uint2*>(blo + i * BP + c4) = make_uint2(bf2u(l01), bf2u(l23));
    }
    stage_T(smb, yh, tid);
    // ---- W staging ----
#pragma unroll
    for (int t = 0; t < 4; t++) {
        int qidx = tid * 4 + t;
        int o = qidx >> 4, ip = (qidx & 15) * 4;
        float4 wv = *reinterpret_cast<const float4*>(cw + o * 64 + ip);
        __nv_bfloat162 h01 = __floats2bfloat162_rn(wv.x, wv.y);
        __nv_bfloat162 h23 = __floats2bfloat162_rn(wv.z, wv.w);
        __nv_bfloat162 l01 = __floats2bfloat162_rn(wv.x - __low2float(h01), wv.y - __high2float(h01));
        __nv_bfloat162 l23 = __floats2bfloat162_rn(wv.z - __low2float(h23), wv.w - __high2float(h23));
        *reinterpret_cast<uint2*>(ahi + o * AP + ip) = make_uint2(bf2u(h01), bf2u(h23));
        *reinterpret_cast<uint2*>(alo + o * AP + ip) = make_uint2(bf2u(l01), bf2u(l23));
    }
    // ---- G staging ----
    if (hasSpec) {
#pragma unroll
        for (int t = 0; t < 2; t++) {
            int cidx = tid * 2 + t;
            int o = cidx >> 3, k2p = (cidx & 7) * 2;
            float4 g = *reinterpret_cast<const float4*>(
                g_gx + (((size_t)(b * 64 + o) * 256 + xx) << 5) + 2 * k2p);
            float d0 = (k2p > 0) ? 2.f : 1.f;
            float a0 = d0 * g.x, a1 = d0 * g.y, a2 = 2.f * g.z, a3 = 2.f * g.w;
            __nv_bfloat162 h01 = __floats2bfloat162_rn(a0, a1);
            __nv_bfloat162 h23 = __floats2bfloat162_rn(a2, a3);
            __nv_bfloat162 l01 = __floats2bfloat162_rn(a0 - __low2float(h01), a1 - __high2float(h01));
            __nv_bfloat162 l23 = __floats2bfloat162_rn(a2 - __low2float(h23), a3 - __high2float(h23));
            *reinterpret_cast<uint2*>(ahi + o * AP + 64 + 2 * k2p) = make_uint2(bf2u(h01), bf2u(h23));
            *reinterpret_cast<uint2*>(alo + o * AP + 64 + 2 * k2p) = make_uint2(bf2u(l01), bf2u(l23));
        }
    }
    if (tid < 64) cbs[tid] = cb[tid];
    if (doHead) {
        if (tid < 64) reinterpret_cast<float*>(smb + CV_HW)[tid] = hw[tid];
        if (tid == 0) reinterpret_cast<float*>(smb + CV_HB)[0] = hb[0];
    }
    __syncthreads();

    int w    = tid >> 5, lane = tid & 31;
    int obase = (w & 1) * 32;
    int ygrp  = w >> 1;
    int rowt = lane >> 2, col = lane & 3;

    float dh[2][4][4], dc[2][4][4];
#pragma unroll
    for (int a = 0; a < 2; a++)
#pragma unroll
        for (int j = 0; j < 4; j++)
#pragma unroll
            for (int c = 0; c < 4; c++) { dh[a][j][c] = 0.f; dc[a][j][c] = 0.f; }

    {
        int mat = lane >> 3;
        int arow = obase + ((mat & 1) << 3) + (lane & 7);
        int kh = (mat >> 1) << 3;
        u32 a0_hi = sptr(ahi) + (u32)(arow * AP + kh) * 2;
        u32 a0_lo = sptr(alo) + (u32)(arow * AP + kh) * 2;
        u32 a1_hi = a0_hi + 16 * AP * 2;
        u32 a1_lo = a0_lo + 16 * AP * 2;
        // x4t B: t0-15 -> rows (lane&15), col y0; t16-31 -> same rows, col y0+8
        u32 bb = (u32)((lane & 15) * BP + ((lane >> 4) << 3)) * 2;
        u32 bbase_hi = sptr(bhi) + bb;
        u32 bbase_lo = sptr(blo) + bb;
        int kLim = hasSpec ? 6 : 4;
#pragma unroll 2
        for (int k = 0; k < kLim; k++) {
            u32 Ah0[4], Al0[4], Ah1[4], Al1[4];
            ldsm_x4(Ah0, a0_hi + k * 32);
            ldsm_x4(Al0, a0_lo + k * 32);
            ldsm_x4(Ah1, a1_hi + k * 32);
            ldsm_x4(Al1, a1_lo + k * 32);
#pragma unroll
            for (int jp = 0; jp < 2; jp++) {
                u32 off = (u32)(k * 16 * BP + ygrp * 32 + jp * 16) * 2;
                u32 Bh[4], Bl[4];
                ldsm_x4t(Bh, bbase_hi + off);
                ldsm_x4t(Bl, bbase_lo + off);
#pragma unroll
                for (int h = 0; h < 2; h++) {
                    int j = jp * 2 + h;
                    u32 b0 = Bh[2 * h], b1 = Bh[2 * h + 1];
                    u32 c0 = Bl[2 * h], c1 = Bl[2 * h + 1];
                    mma_bf16(dh[0][j], Ah0, b0, b1);
                    mma_bf16(dc[0][j], Ah0, c0, c1);
                    mma_bf16(dc[0][j], Al0, b0, b1);
                    mma_bf16(dh[1][j], Ah1, b0, b1);
                    mma_bf16(dc[1][j], Ah1, c0, c1);
                    mma_bf16(dc[1][j], Al1, b0, b1);
                }
            }
        }
    }

    // ---- epilogue: merge + bias + exact GELU ----
    __syncthreads();
    float* res = smf;
#pragma unroll
    for (int a = 0; a < 2; a++) {
#pragma unroll
        for (int j = 0; j < 4; j++) {
            int y0 = ygrp * 32 + j * 8 + col * 2;
#pragma unroll
            for (int r = 0; r < 2; r++) {
                int o = obase + a * 16 + rowt + 8 * r;
                float bias = cbs[o];
                float p = dh[a][j][2 * r]     + dc[a][j][2 * r]     + bias;
                float q = dh[a][j][2 * r + 1] + dc[a][j][2 * r + 1] + bias;
                float gp = 0.5f * p * (1.0f + erff(p * 0.70710678118654752f));
                float gq = 0.5f * q * (1.0f + erff(q * 0.70710678118654752f));
                if (doFy) {
                    __nv_bfloat162 h2 = __floats2bfloat162_rn(gp, gq);
                    __nv_bfloat162 l2 = __floats2bfloat162_rn(gp - __low2float(h2), gq - __high2float(h2));
                    *reinterpret_cast<__nv_bfloat162*>(bhi + o * BP + y0) = h2;
                    *reinterpret_cast<__nv_bfloat162*>(blo + o * BP + y0) = l2;
                }
                if (doHead)
                    *reinterpret_cast<float2*>(res + o * SRH + y0) = make_float2(gp, gq);
                if (!doHead)
                    *reinterpret_cast<float2*>(hout + ((size_t)(b * 64 + o) << 16) +
                                               xx * 256 + yh * 128 + y0) = make_float2(gp, gq);
            }
        }
    }

    if (doFy) {
        __syncthreads();
        fy_mma(smb, b, xx, yh, w, lane);
    }
    if (doHead) {
        __syncthreads();
        if (tid < 128) {
            const float* hwS = reinterpret_cast<const float*>(smb + CV_HW);
            float a = reinterpret_cast<const float*>(smb + CV_HB)[0];
            int y = tid;
#pragma unroll 16
            for (int f = 0; f < 64; f++) a = fmaf(res[f * SRH + y], hwS[f], a);
            out[(size_t)b * 65536 + xx * 256 + yh * 128 + y] = a;
        }
    }
}

// ---------------- launch ----------------
extern "C" void kernel_launch(void* const* d_in, const int* in_sizes, int n_in,
                              void* d_out, int out_size) {
    const float* x     = (const float*)d_in[0];
    const float* fc0_w = (const float*)d_in[1];
    const float* fc0_b = (const float*)d_in[2];
    const float* sw[4] = {(const float*)d_in[3], (const float*)d_in[4],
                          (const float*)d_in[5], (const float*)d_in[6]};
    const float* cw[4] = {(const float*)d_in[7], (const float*)d_in[9],
                          (const float*)d_in[11], (const float*)d_in[13]};
    const float* cb[4] = {(const float*)d_in[8], (const float*)d_in[10],
                          (const float*)d_in[12], (const float*)d_in[14]};
    const float* fc1_w = (const float*)d_in[15];
    const float* fc1_b = (const float*)d_in[16];
    const float* fc2_w = (const float*)d_in[17];
    const float* fc2_b = (const float*)d_in[18];
    float* out = (float*)d_out;

    cudaFuncSetAttribute(conv_mma, cudaFuncAttributeMaxDynamicSharedMemorySize, CONV_SMEM);
    cudaFuncSetAttribute(fc0_fy,   cudaFuncAttributeMaxDynamicSharedMemorySize, F0_SMEM);

    init_tab_kernel<<<1, 256>>>();
    init_T_kernel<<<32, 256>>>();
    sw_transpose<<<2048, 256>>>(sw[0], sw[1], sw[2], sw[3]);
    fc0_fy<<<8192, 256, F0_SMEM>>>(x, fc0_w, fc0_b);

    int src = 0;
    for (int l = 0; l < 4; l++) {
        dftx_fwd<<<1024, 256>>>();
        mode_mix<<<256, 256>>>(l);
        dftx_inv<<<1024, 256>>>();
        int doFy = (l < 3) ? 1 : 0;
        conv_mma<<<8192, 256, CONV_SMEM>>>(src, 1 - src, cw[l], cb[l],
                                           1, doFy, 0, nullptr, nullptr, nullptr);
        src = 1 - src;
    }
    conv_mma<<<8192, 256, CONV_SMEM>>>(src, src, fc1_w, fc1_b,
                                       0, 0, 1, fc2_w, fc2_b, out);
}